// round 14
// baseline (speedup 1.0000x reference)
#include <cuda_runtime.h>
#include <cstdint>

#define NMAX 100000
#define D 64
#define EMAX 1700000

// Scratch (static __device__ globals; allocation in kernel_launch is forbidden)
__device__ int   g_is64;                            // 1 if edge_index is int64, 0 if int32
__device__ float g_dinv[NMAX];                      // rsqrt(degree) (incl. self loop)
__device__ float4 g_h[NMAX * (D / 4)];              // GEMM output, float4-aligned
__device__ float4 g_a[NMAX * (D / 4)];              // layer-1 aggregation output
__device__ int2  g_esd[EMAX];                       // per-edge {src, dst} as int32
__device__ float g_enorm[EMAX];                     // per-edge dinv[src]*dinv[dst]

// ---------------------------------------------------------------------------
// Dtype probe: node ids are < 100000 (< 2^32). If the buffer is int64, every
// 8-byte word has a zero upper half. If it is int32 (JAX x64 disabled), words
// pack two indices and upper halves are nonzero with prob ~1 - 1e-5 each.
// ---------------------------------------------------------------------------
__global__ void detect_dtype_kernel(const unsigned long long* __restrict__ ei, int nwords) {
    if (threadIdx.x != 0 || blockIdx.x != 0) return;
    int is64 = 1;
    for (int i = 0; i < nwords; i++)
        if (ei[i] > 0xFFFFFFFFULL) { is64 = 0; break; }
    g_is64 = is64;
}

// ---------------------------------------------------------------------------
// Decode edges into int2 records (handles both int32 and int64 layouts).
// Row-major (2, E): src = row 0, dst = row 1. Indices clamped to [0, n) so a
// wrong dtype/layout theory yields a measurable rel_err instead of a trap.
// ---------------------------------------------------------------------------
__global__ void decode_edges_kernel(const void* __restrict__ ei, int2* __restrict__ esd,
                                    int E, int n) {
    int e = blockIdx.x * blockDim.x + threadIdx.x;
    if (e >= E) return;
    int s, d;
    if (g_is64) {
        const long long* p = (const long long*)ei;
        s = (int)p[e];
        d = (int)p[E + e];
    } else {
        const int* p = (const int*)ei;
        s = p[e];
        d = p[E + e];
    }
    s = min(max(s, 0), n - 1);
    d = min(max(d, 0), n - 1);
    esd[e] = make_int2(s, d);
}

// ---------------------------------------------------------------------------
// Degree: zero, count dst occurrences, finalize dinv = rsqrt(deg + 1)
// ---------------------------------------------------------------------------
__global__ void zero_deg_kernel(float* deg, int n) {
    int i = blockIdx.x * blockDim.x + threadIdx.x;
    if (i < n) deg[i] = 0.0f;
}

__global__ void count_deg_kernel(const int2* __restrict__ esd, float* deg, int E) {
    int e = blockIdx.x * blockDim.x + threadIdx.x;
    if (e < E) atomicAdd(&deg[__ldg(&esd[e]).y], 1.0f);
}

__global__ void finalize_dinv_kernel(float* dinv, int n) {
    int i = blockIdx.x * blockDim.x + threadIdx.x;
    if (i < n) dinv[i] = rsqrtf(dinv[i] + 1.0f);  // +1 self loop; always > 0
}

// ---------------------------------------------------------------------------
// Per-edge norm (once, shared by both layers): enorm[e] = dinv[src]*dinv[dst]
// ---------------------------------------------------------------------------
__global__ void edge_norm_kernel(const int2* __restrict__ esd, const float* __restrict__ dinv,
                                 float* __restrict__ enorm, int E) {
    int e = blockIdx.x * blockDim.x + threadIdx.x;
    if (e >= E) return;
    int2 sd = __ldg(&esd[e]);
    enorm[e] = __ldg(&dinv[sd.x]) * __ldg(&dinv[sd.y]);
}

// ---------------------------------------------------------------------------
// Fused GEMM + accumulator init:
//   h[i][j]   = sum_k X[i][k] * W[j][k]              (H = X @ W^T)
//   acc[i][j] = h[i][j] * dinv[i]^2 + b[j]           (self-loop + bias)
// Block: 256 threads = 4 nodes x 64 output cols. W staged in padded smem.
// ---------------------------------------------------------------------------
__global__ void gemm_init_kernel(const float* __restrict__ X, const float* __restrict__ W,
                                 const float* __restrict__ b, const float* __restrict__ dinv,
                                 float* __restrict__ H, float* __restrict__ acc, int n) {
    __shared__ float Ws[D][D + 1];   // +1 pad: conflict-free Ws[j][k] across j
    __shared__ float Xs[4][D];
    int t = threadIdx.x;
    for (int i = t; i < D * D; i += 256) Ws[i >> 6][i & 63] = W[i];

    int local = t >> 6;          // 0..3
    int j     = t & 63;          // output column
    int node  = blockIdx.x * 4 + local;
    if (node < n) Xs[local][j] = X[node * D + j];
    __syncthreads();
    if (node >= n) return;

    float sum = 0.0f;
#pragma unroll
    for (int k = 0; k < D; k++) sum += Xs[local][k] * Ws[j][k];

    float s = dinv[node];
    H[node * D + j]   = sum;
    acc[node * D + j] = sum * (s * s) + b[j];
}

// ---------------------------------------------------------------------------
// Edge aggregation: acc[dst] += h[src] * norm
// 16 threads per edge, one float4 each, via the documented vector
// atomicAdd(float4*) (cc >= 9.0); result discarded -> no-return reduction.
// ---------------------------------------------------------------------------
__global__ void edge_agg_kernel(const int2* __restrict__ esd,
                                const float* __restrict__ enorm,
                                const float4* __restrict__ h,
                                float4* __restrict__ acc, int E) {
    unsigned tid = blockIdx.x * blockDim.x + threadIdx.x;
    int e    = tid >> 4;
    int lane = tid & 15;
    if (e >= E) return;
    int2  sd   = __ldg(&esd[e]);
    float norm = __ldg(&enorm[e]);
    float4 v = __ldg(&h[sd.x * (D / 4) + lane]);
    float4 m = make_float4(v.x * norm, v.y * norm, v.z * norm, v.w * norm);
    atomicAdd(&acc[sd.y * (D / 4) + lane], m);
}

// ---------------------------------------------------------------------------
extern "C" void kernel_launch(void* const* d_in, const int* in_sizes, int n_in,
                              void* d_out, int out_size) {
    const float* x  = (const float*)d_in[0];
    const void*  ei = d_in[1];                 // int32 or int64, probed on device
    const float* W1 = (const float*)d_in[2];
    const float* b1 = (const float*)d_in[3];
    const float* W2 = (const float*)d_in[4];
    const float* b2 = (const float*)d_in[5];
    float*       out = (float*)d_out;

    int n = in_sizes[0] / D;        // 100000
    int E = in_sizes[1] / 2;        // 1600000 (element count is dtype-independent)

    float  *dinv, *enorm;
    float4 *h, *a;
    int2   *esd;
    cudaGetSymbolAddress((void**)&dinv,  g_dinv);
    cudaGetSymbolAddress((void**)&h,     g_h);
    cudaGetSymbolAddress((void**)&a,     g_a);
    cudaGetSymbolAddress((void**)&esd,   g_esd);
    cudaGetSymbolAddress((void**)&enorm, g_enorm);

    const int TB = 256;
    int nodeBlocks  = (n + TB - 1) / TB;
    int edgeBlocks  = (E + TB - 1) / TB;
    int gemmBlocks  = (n + 3) / 4;
    long long et    = (long long)E * 16;               // 16 threads/edge
    int edgeAggBlocks = (int)((et + TB - 1) / TB);

    // Probe index dtype, decode edges, then degree -> dinv -> per-edge norms
    int probeWords = E < 256 ? E : 256;  // int32: reads 2*probeWords indices; in-bounds either way
    detect_dtype_kernel<<<1, 32>>>((const unsigned long long*)ei, probeWords);
    decode_edges_kernel<<<edgeBlocks, TB>>>(ei, esd, E, n);
    zero_deg_kernel<<<nodeBlocks, TB>>>(dinv, n);
    count_deg_kernel<<<edgeBlocks, TB>>>(esd, dinv, E);
    finalize_dinv_kernel<<<nodeBlocks, TB>>>(dinv, n);
    edge_norm_kernel<<<edgeBlocks, TB>>>(esd, dinv, enorm, E);

    // Layer 1: h = x @ W1^T (fused self-loop+bias init into a), then a += edges
    gemm_init_kernel<<<gemmBlocks, TB>>>(x, W1, b1, dinv, (float*)h, (float*)a, n);
    edge_agg_kernel<<<edgeAggBlocks, TB>>>(esd, enorm, h, a, E);

    // Layer 2: h = a @ W2^T (fused init into out), then out += edges
    gemm_init_kernel<<<gemmBlocks, TB>>>((const float*)a, W2, b2, dinv, (float*)h, out, n);
    edge_agg_kernel<<<edgeAggBlocks, TB>>>(esd, enorm, h, (float4*)out, E);
}

// round 15
// speedup vs baseline: 1.7223x; 1.7223x over previous
#include <cuda_runtime.h>
#include <cstdint>

#define NMAX 100000
#define D 64
#define EMAX 1700000
#define TB 256

// Scratch (static __device__ globals; allocation in kernel_launch is forbidden)
__device__ int    g_is64;                  // 1 if edge_index is int64, 0 if int32
__device__ int    g_deg[NMAX];             // in-degree (excl. self loop)
__device__ int    g_cnt[NMAX];             // scatter cursors
__device__ int    g_rowptr[NMAX];          // CSR row starts (exclusive scan of deg)
__device__ int    g_bsum[1024];            // per-block sums for scan
__device__ float  g_dinv[NMAX];            // rsqrt(deg + 1)
__device__ int2   g_esd[EMAX];             // decoded {src, dst}
__device__ int2   g_csr[EMAX];             // dst-sorted records {src, norm-as-int}
__device__ float4 g_h[NMAX * (D / 4)];     // GEMM output
__device__ float4 g_a[NMAX * (D / 4)];     // layer-1 output

// ---------------------------------------------------------------------------
// Dtype probe: ids < 1e5 << 2^32; int64 words have zero upper halves.
// ---------------------------------------------------------------------------
__global__ void detect_dtype_kernel(const unsigned long long* __restrict__ ei, int nwords) {
    if (threadIdx.x != 0 || blockIdx.x != 0) return;
    int is64 = 1;
    for (int i = 0; i < nwords; i++)
        if (ei[i] > 0xFFFFFFFFULL) { is64 = 0; break; }
    g_is64 = is64;
}

__global__ void zero_int2_kernel(int* a, int* b, int n) {
    int i = blockIdx.x * blockDim.x + threadIdx.x;
    if (i < n) { a[i] = 0; b[i] = 0; }
}

// Decode edges (both dtypes), clamp, count in-degree.
__global__ void decode_count_kernel(const void* __restrict__ ei, int2* __restrict__ esd,
                                    int* __restrict__ deg, int E, int n) {
    int e = blockIdx.x * blockDim.x + threadIdx.x;
    if (e >= E) return;
    int s, d;
    if (g_is64) {
        const long long* p = (const long long*)ei;
        s = (int)p[e]; d = (int)p[E + e];
    } else {
        const int* p = (const int*)ei;
        s = p[e]; d = p[E + e];
    }
    s = min(max(s, 0), n - 1);
    d = min(max(d, 0), n - 1);
    esd[e] = make_int2(s, d);
    atomicAdd(&deg[d], 1);
}

// ---- exclusive prefix sum of deg -> rowptr (3 small kernels) --------------
__global__ void scan_block_sums(const int* __restrict__ deg, int* __restrict__ bsum, int n) {
    __shared__ int sm[TB];
    int i = blockIdx.x * TB + threadIdx.x;
    sm[threadIdx.x] = (i < n) ? deg[i] : 0;
    __syncthreads();
    for (int off = TB / 2; off > 0; off >>= 1) {
        if (threadIdx.x < off) sm[threadIdx.x] += sm[threadIdx.x + off];
        __syncthreads();
    }
    if (threadIdx.x == 0) bsum[blockIdx.x] = sm[0];
}

__global__ void scan_bsums_kernel(int* __restrict__ bsum, int nb) {  // single block of 1024
    __shared__ int sm[1024];
    int t = threadIdx.x;
    int v = (t < nb) ? bsum[t] : 0;
    sm[t] = v;
    __syncthreads();
    for (int off = 1; off < 1024; off <<= 1) {
        int add = (t >= off) ? sm[t - off] : 0;
        __syncthreads();
        sm[t] += add;
        __syncthreads();
    }
    if (t < nb) bsum[t] = sm[t] - v;   // exclusive
}

__global__ void scan_final_kernel(const int* __restrict__ deg, const int* __restrict__ bsum,
                                  int* __restrict__ rowptr, int n) {
    __shared__ int sm[TB];
    int i = blockIdx.x * TB + threadIdx.x;
    int t = threadIdx.x;
    int v = (i < n) ? deg[i] : 0;
    sm[t] = v;
    __syncthreads();
    for (int off = 1; off < TB; off <<= 1) {
        int add = (t >= off) ? sm[t - off] : 0;
        __syncthreads();
        sm[t] += add;
        __syncthreads();
    }
    if (i < n) rowptr[i] = bsum[blockIdx.x] + sm[t] - v;   // exclusive scan
}

__global__ void finalize_dinv_kernel(const int* __restrict__ deg, float* __restrict__ dinv, int n) {
    int i = blockIdx.x * blockDim.x + threadIdx.x;
    if (i < n) dinv[i] = rsqrtf((float)deg[i] + 1.0f);   // +1 self loop
}

// Scatter edges into dst-sorted CSR with per-edge norm baked in.
__global__ void scatter_csr_kernel(const int2* __restrict__ esd, const float* __restrict__ dinv,
                                   const int* __restrict__ rowptr, int* __restrict__ cnt,
                                   int2* __restrict__ csr, int E) {
    int e = blockIdx.x * blockDim.x + threadIdx.x;
    if (e >= E) return;
    int2 sd = __ldg(&esd[e]);
    float nm = __ldg(&dinv[sd.x]) * __ldg(&dinv[sd.y]);
    int pos = __ldg(&rowptr[sd.y]) + atomicAdd(&cnt[sd.y], 1);
    csr[pos] = make_int2(sd.x, __float_as_int(nm));
}

// ---------------------------------------------------------------------------
// GEMM H = X @ W^T, register-tiled: block = 16 nodes x 64 cols, each thread
// computes 4 nodes for one output col -> 4 FFMA per Ws LDS (4x less LDS/FFMA).
// ---------------------------------------------------------------------------
__global__ void gemm_kernel(const float* __restrict__ X, const float* __restrict__ W,
                            float* __restrict__ H, int n) {
    __shared__ float Ws[D][D + 1];
    __shared__ float Xs[16][D];
    int t = threadIdx.x;
    for (int i = t; i < D * D; i += TB) Ws[i >> 6][i & 63] = W[i];
    int base = blockIdx.x * 16;
    for (int i = t; i < 16 * D; i += TB) {
        int row = i >> 6, col = i & 63;
        int node = base + row;
        Xs[row][col] = (node < n) ? X[node * D + col] : 0.0f;
    }
    __syncthreads();

    int j  = t & 63;          // output column
    int rg = t >> 6;          // 0..3 -> nodes rg*4 .. rg*4+3
    float a0 = 0.f, a1 = 0.f, a2 = 0.f, a3 = 0.f;
#pragma unroll
    for (int k = 0; k < D; k++) {
        float w = Ws[j][k];
        a0 = fmaf(w, Xs[rg * 4 + 0][k], a0);
        a1 = fmaf(w, Xs[rg * 4 + 1][k], a1);
        a2 = fmaf(w, Xs[rg * 4 + 2][k], a2);
        a3 = fmaf(w, Xs[rg * 4 + 3][k], a3);
    }
    int node = base + rg * 4;
    if (node + 0 < n) H[(node + 0) * D + j] = a0;
    if (node + 1 < n) H[(node + 1) * D + j] = a1;
    if (node + 2 < n) H[(node + 2) * D + j] = a2;
    if (node + 3 < n) H[(node + 3) * D + j] = a3;
}

// ---------------------------------------------------------------------------
// Pull aggregation (atomic-free):
//   out[i] = b + dinv[i]^2 * h[i] + sum_{e: dst=i} norm_e * h[src_e]
// 16 lanes per node, one float4 chunk each; edges walked from CSR.
// ---------------------------------------------------------------------------
__global__ void pull_kernel(const int2* __restrict__ csr, const int* __restrict__ rowptr,
                            const int* __restrict__ deg, const float* __restrict__ dinv,
                            const float4* __restrict__ b4, const float4* __restrict__ h,
                            float4* __restrict__ out, int n) {
    int i = blockIdx.x * 16 + (threadIdx.x >> 4);
    int l = threadIdx.x & 15;
    if (i >= n) return;

    float s  = __ldg(&dinv[i]);
    float s2 = s * s;
    float4 acc = __ldg(&b4[l]);
    float4 hv  = __ldg(&h[i * 16 + l]);
    acc.x = fmaf(s2, hv.x, acc.x);
    acc.y = fmaf(s2, hv.y, acc.y);
    acc.z = fmaf(s2, hv.z, acc.z);
    acc.w = fmaf(s2, hv.w, acc.w);

    int start = __ldg(&rowptr[i]);
    int m     = __ldg(&deg[i]);
    int j = 0;
    for (; j + 2 <= m; j += 2) {          // 2-way unroll for MLP
        int2 r0 = __ldg(&csr[start + j]);
        int2 r1 = __ldg(&csr[start + j + 1]);
        float4 v0 = __ldg(&h[r0.x * 16 + l]);
        float4 v1 = __ldg(&h[r1.x * 16 + l]);
        float n0 = __int_as_float(r0.y);
        float n1 = __int_as_float(r1.y);
        acc.x = fmaf(n0, v0.x, acc.x); acc.y = fmaf(n0, v0.y, acc.y);
        acc.z = fmaf(n0, v0.z, acc.z); acc.w = fmaf(n0, v0.w, acc.w);
        acc.x = fmaf(n1, v1.x, acc.x); acc.y = fmaf(n1, v1.y, acc.y);
        acc.z = fmaf(n1, v1.z, acc.z); acc.w = fmaf(n1, v1.w, acc.w);
    }
    if (j < m) {
        int2 r0 = __ldg(&csr[start + j]);
        float4 v0 = __ldg(&h[r0.x * 16 + l]);
        float n0 = __int_as_float(r0.y);
        acc.x = fmaf(n0, v0.x, acc.x); acc.y = fmaf(n0, v0.y, acc.y);
        acc.z = fmaf(n0, v0.z, acc.z); acc.w = fmaf(n0, v0.w, acc.w);
    }
    out[i * 16 + l] = acc;
}

// ---------------------------------------------------------------------------
extern "C" void kernel_launch(void* const* d_in, const int* in_sizes, int n_in,
                              void* d_out, int out_size) {
    const float* x  = (const float*)d_in[0];
    const void*  ei = d_in[1];
    const float* W1 = (const float*)d_in[2];
    const float* b1 = (const float*)d_in[3];
    const float* W2 = (const float*)d_in[4];
    const float* b2 = (const float*)d_in[5];
    float*       out = (float*)d_out;

    int n = in_sizes[0] / D;        // 100000
    int E = in_sizes[1] / 2;        // 1600000

    int *deg, *cnt, *rowptr, *bsum;
    float *dinv;
    int2 *esd, *csr;
    float4 *h, *a;
    cudaGetSymbolAddress((void**)&deg,    g_deg);
    cudaGetSymbolAddress((void**)&cnt,    g_cnt);
    cudaGetSymbolAddress((void**)&rowptr, g_rowptr);
    cudaGetSymbolAddress((void**)&bsum,   g_bsum);
    cudaGetSymbolAddress((void**)&dinv,   g_dinv);
    cudaGetSymbolAddress((void**)&esd,    g_esd);
    cudaGetSymbolAddress((void**)&csr,    g_csr);
    cudaGetSymbolAddress((void**)&h,      g_h);
    cudaGetSymbolAddress((void**)&a,      g_a);

    int nodeBlocks = (n + TB - 1) / TB;           // 391 (fits bsum[1024] / 1024-thread scan)
    int edgeBlocks = (E + TB - 1) / TB;
    int tileBlocks = (n + 15) / 16;               // 6250: gemm + pull grids

    // Prologue: probe dtype, decode + degree, prefix sum, dinv, scatter CSR
    int probeWords = E < 256 ? E : 256;
    detect_dtype_kernel<<<1, 32>>>((const unsigned long long*)ei, probeWords);
    zero_int2_kernel<<<nodeBlocks, TB>>>(deg, cnt, n);
    decode_count_kernel<<<edgeBlocks, TB>>>(ei, esd, deg, E, n);
    scan_block_sums<<<nodeBlocks, TB>>>(deg, bsum, n);
    scan_bsums_kernel<<<1, 1024>>>(bsum, nodeBlocks);
    scan_final_kernel<<<nodeBlocks, TB>>>(deg, bsum, rowptr, n);
    finalize_dinv_kernel<<<nodeBlocks, TB>>>(deg, dinv, n);
    scatter_csr_kernel<<<edgeBlocks, TB>>>(esd, dinv, rowptr, cnt, csr, E);

    // Layer 1
    gemm_kernel<<<tileBlocks, TB>>>(x, W1, (float*)h, n);
    pull_kernel<<<tileBlocks, TB>>>(csr, rowptr, deg, dinv, (const float4*)b1, h, a, n);

    // Layer 2
    gemm_kernel<<<tileBlocks, TB>>>((const float*)a, W2, (float*)h, n);
    pull_kernel<<<tileBlocks, TB>>>(csr, rowptr, deg, dinv, (const float4*)b2, h, (float4*)out, n);
}

// round 17
// speedup vs baseline: 1.9644x; 1.1406x over previous
#include <cuda_runtime.h>
#include <cstdint>

#define NMAX 100000
#define D 64
#define EMAX 1700000
#define TB 256

// Scratch (static __device__ globals; allocation in kernel_launch is forbidden)
__device__ int    g_is64;
__device__ int    g_deg[NMAX];             // in-degree (excl. self loop)
__device__ int    g_cnt[NMAX];             // scatter cursors
__device__ int    g_rowptr[NMAX];          // CSR row starts
__device__ int    g_bsum[1024];
__device__ float  g_dinv[NMAX];            // rsqrt(deg + 1)
__device__ int2   g_esd[EMAX];             // decoded {src, dst}
__device__ int2   g_csr[EMAX];             // dst-sorted {src, norm-as-int}
__device__ float4 g_h[NMAX * (D / 4)];
__device__ float4 g_a[NMAX * (D / 4)];

// ---------------------------------------------------------------------------
__global__ void detect_dtype_kernel(const unsigned long long* __restrict__ ei, int nwords) {
    if (threadIdx.x != 0 || blockIdx.x != 0) return;
    int is64 = 1;
    for (int i = 0; i < nwords; i++)
        if (ei[i] > 0xFFFFFFFFULL) { is64 = 0; break; }
    g_is64 = is64;
}

__global__ void zero_deg_kernel(int* deg, int n) {
    int i = blockIdx.x * blockDim.x + threadIdx.x;
    if (i < n) deg[i] = 0;
}

__global__ void decode_count_kernel(const void* __restrict__ ei, int2* __restrict__ esd,
                                    int* __restrict__ deg, int E, int n) {
    int e = blockIdx.x * blockDim.x + threadIdx.x;
    if (e >= E) return;
    int s, d;
    if (g_is64) {
        const long long* p = (const long long*)ei;
        s = (int)p[e]; d = (int)p[E + e];
    } else {
        const int* p = (const int*)ei;
        s = p[e]; d = p[E + e];
    }
    s = min(max(s, 0), n - 1);
    d = min(max(d, 0), n - 1);
    esd[e] = make_int2(s, d);
    atomicAdd(&deg[d], 1);
}

// ---- exclusive prefix sum of deg -> rowptr -------------------------------
__global__ void scan_block_sums(const int* __restrict__ deg, int* __restrict__ bsum, int n) {
    __shared__ int sm[TB];
    int i = blockIdx.x * TB + threadIdx.x;
    sm[threadIdx.x] = (i < n) ? deg[i] : 0;
    __syncthreads();
    for (int off = TB / 2; off > 0; off >>= 1) {
        if (threadIdx.x < off) sm[threadIdx.x] += sm[threadIdx.x + off];
        __syncthreads();
    }
    if (threadIdx.x == 0) bsum[blockIdx.x] = sm[0];
}

__global__ void scan_bsums_kernel(int* __restrict__ bsum, int nb) {  // single 1024-thread block
    __shared__ int sm[1024];
    int t = threadIdx.x;
    int v = (t < nb) ? bsum[t] : 0;
    sm[t] = v;
    __syncthreads();
    for (int off = 1; off < 1024; off <<= 1) {
        int add = (t >= off) ? sm[t - off] : 0;
        __syncthreads();
        sm[t] += add;
        __syncthreads();
    }
    if (t < nb) bsum[t] = sm[t] - v;   // exclusive
}

// scan_final also finalizes dinv and zeroes cnt (fused; saves 2 launches)
__global__ void scan_final_kernel(const int* __restrict__ deg, const int* __restrict__ bsum,
                                  int* __restrict__ rowptr, float* __restrict__ dinv,
                                  int* __restrict__ cnt, int n) {
    __shared__ int sm[TB];
    int i = blockIdx.x * TB + threadIdx.x;
    int t = threadIdx.x;
    int v = (i < n) ? deg[i] : 0;
    sm[t] = v;
    __syncthreads();
    for (int off = 1; off < TB; off <<= 1) {
        int add = (t >= off) ? sm[t - off] : 0;
        __syncthreads();
        sm[t] += add;
        __syncthreads();
    }
    if (i < n) {
        rowptr[i] = bsum[blockIdx.x] + sm[t] - v;   // exclusive scan
        dinv[i]   = rsqrtf((float)v + 1.0f);        // +1 self loop
        cnt[i]    = 0;
    }
}

__global__ void scatter_csr_kernel(const int2* __restrict__ esd, const float* __restrict__ dinv,
                                   const int* __restrict__ rowptr, int* __restrict__ cnt,
                                   int2* __restrict__ csr, int E) {
    int e = blockIdx.x * blockDim.x + threadIdx.x;
    if (e >= E) return;
    int2 sd = __ldg(&esd[e]);
    float nm = __ldg(&dinv[sd.x]) * __ldg(&dinv[sd.y]);
    int pos = __ldg(&rowptr[sd.y]) + atomicAdd(&cnt[sd.y], 1);
    csr[pos] = make_int2(sd.x, __float_as_int(nm));
}

// ---------------------------------------------------------------------------
// GEMM H = X @ W^T, 64-node tile, 4x4 register tile per thread.
// Xs[k][r] (k-major), Ws[k][j] (k-major) -> 2 LDS.128 per 16 FFMA.
// Stride 68 floats keeps float4 16B alignment for any r4/c4 multiple of 4.
// ---------------------------------------------------------------------------
__global__ void gemm_kernel(const float* __restrict__ X, const float* __restrict__ W,
                            float* __restrict__ H, int n) {
    __shared__ float Xs[D][68];   // Xs[k][r] = X[base+r][k]
    __shared__ float Ws[D][68];   // Ws[k][j] = W[j][k]
    int t = threadIdx.x;
    int base = blockIdx.x * 64;

    for (int i = t; i < D * D; i += TB) {
        int r = i >> 6, k = i & 63;                 // consecutive k per thread-step
        int node = base + r;
        Xs[k][r] = (node < n) ? X[node * D + k] : 0.0f;
        Ws[k][r] = W[r * D + k];                    // r plays "j" here
    }
    __syncthreads();

    int c4 = (t & 15) * 4;        // output cols c4..c4+3
    int r4 = (t >> 4) * 4;        // rows r4..r4+3
    float acc[4][4];
#pragma unroll
    for (int i = 0; i < 4; i++)
#pragma unroll
        for (int j = 0; j < 4; j++) acc[i][j] = 0.0f;

#pragma unroll
    for (int k = 0; k < D; k++) {
        float4 xv = *reinterpret_cast<const float4*>(&Xs[k][r4]);
        float4 wv = *reinterpret_cast<const float4*>(&Ws[k][c4]);
        float xr[4] = {xv.x, xv.y, xv.z, xv.w};
        float wr[4] = {wv.x, wv.y, wv.z, wv.w};
#pragma unroll
        for (int i = 0; i < 4; i++)
#pragma unroll
            for (int j = 0; j < 4; j++)
                acc[i][j] = fmaf(xr[i], wr[j], acc[i][j]);
    }

#pragma unroll
    for (int i = 0; i < 4; i++) {
        int node = base + r4 + i;
        if (node < n) {
            float4 o = make_float4(acc[i][0], acc[i][1], acc[i][2], acc[i][3]);
            *reinterpret_cast<float4*>(&H[node * D + c4]) = o;
        }
    }
}

// ---------------------------------------------------------------------------
// Pull aggregation (atomic-free), 16 lanes/node, 4-way unrolled gather (MLP=4):
//   out[i] = b + dinv[i]^2 * h[i] + sum_{e: dst=i} norm_e * h[src_e]
// ---------------------------------------------------------------------------
__global__ void pull_kernel(const int2* __restrict__ csr, const int* __restrict__ rowptr,
                            const int* __restrict__ deg, const float* __restrict__ dinv,
                            const float4* __restrict__ b4, const float4* __restrict__ h,
                            float4* __restrict__ out, int n) {
    int i = blockIdx.x * 16 + (threadIdx.x >> 4);
    int l = threadIdx.x & 15;
    if (i >= n) return;

    float s  = __ldg(&dinv[i]);
    float s2 = s * s;
    float4 acc = __ldg(&b4[l]);
    float4 hv  = __ldg(&h[i * 16 + l]);
    acc.x = fmaf(s2, hv.x, acc.x);
    acc.y = fmaf(s2, hv.y, acc.y);
    acc.z = fmaf(s2, hv.z, acc.z);
    acc.w = fmaf(s2, hv.w, acc.w);

    int start = __ldg(&rowptr[i]);
    int m     = __ldg(&deg[i]);
    int j = 0;
    for (; j + 4 <= m; j += 4) {
        int2 r0 = __ldg(&csr[start + j + 0]);
        int2 r1 = __ldg(&csr[start + j + 1]);
        int2 r2 = __ldg(&csr[start + j + 2]);
        int2 r3 = __ldg(&csr[start + j + 3]);
        float4 v0 = __ldg(&h[r0.x * 16 + l]);
        float4 v1 = __ldg(&h[r1.x * 16 + l]);
        float4 v2 = __ldg(&h[r2.x * 16 + l]);
        float4 v3 = __ldg(&h[r3.x * 16 + l]);
        float n0 = __int_as_float(r0.y), n1 = __int_as_float(r1.y);
        float n2 = __int_as_float(r2.y), n3 = __int_as_float(r3.y);
        acc.x = fmaf(n0, v0.x, acc.x); acc.y = fmaf(n0, v0.y, acc.y);
        acc.z = fmaf(n0, v0.z, acc.z); acc.w = fmaf(n0, v0.w, acc.w);
        acc.x = fmaf(n1, v1.x, acc.x); acc.y = fmaf(n1, v1.y, acc.y);
        acc.z = fmaf(n1, v1.z, acc.z); acc.w = fmaf(n1, v1.w, acc.w);
        acc.x = fmaf(n2, v2.x, acc.x); acc.y = fmaf(n2, v2.y, acc.y);
        acc.z = fmaf(n2, v2.z, acc.z); acc.w = fmaf(n2, v2.w, acc.w);
        acc.x = fmaf(n3, v3.x, acc.x); acc.y = fmaf(n3, v3.y, acc.y);
        acc.z = fmaf(n3, v3.z, acc.z); acc.w = fmaf(n3, v3.w, acc.w);
    }
    for (; j < m; j++) {
        int2 r0 = __ldg(&csr[start + j]);
        float4 v0 = __ldg(&h[r0.x * 16 + l]);
        float n0 = __int_as_float(r0.y);
        acc.x = fmaf(n0, v0.x, acc.x); acc.y = fmaf(n0, v0.y, acc.y);
        acc.z = fmaf(n0, v0.z, acc.z); acc.w = fmaf(n0, v0.w, acc.w);
    }
    out[i * 16 + l] = acc;
}

// ---------------------------------------------------------------------------
extern "C" void kernel_launch(void* const* d_in, const int* in_sizes, int n_in,
                              void* d_out, int out_size) {
    const float* x  = (const float*)d_in[0];
    const void*  ei = d_in[1];
    const float* W1 = (const float*)d_in[2];
    const float* b1 = (const float*)d_in[3];
    const float* W2 = (const float*)d_in[4];
    const float* b2 = (const float*)d_in[5];
    float*       out = (float*)d_out;

    int n = in_sizes[0] / D;        // 100000
    int E = in_sizes[1] / 2;        // 1600000

    int *deg, *cnt, *rowptr, *bsum;
    float *dinv;
    int2 *esd, *csr;
    float4 *h, *a;
    cudaGetSymbolAddress((void**)&deg,    g_deg);
    cudaGetSymbolAddress((void**)&cnt,    g_cnt);
    cudaGetSymbolAddress((void**)&rowptr, g_rowptr);
    cudaGetSymbolAddress((void**)&bsum,   g_bsum);
    cudaGetSymbolAddress((void**)&dinv,   g_dinv);
    cudaGetSymbolAddress((void**)&esd,    g_esd);
    cudaGetSymbolAddress((void**)&csr,    g_csr);
    cudaGetSymbolAddress((void**)&h,      g_h);
    cudaGetSymbolAddress((void**)&a,      g_a);

    int nodeBlocks = (n + TB - 1) / TB;           // 391 <= 1024
    int edgeBlocks = (E + TB - 1) / TB;
    int gemmBlocks = (n + 63) / 64;               // 1563
    int pullBlocks = (n + 15) / 16;               // 6250

    int probeWords = E < 256 ? E : 256;
    detect_dtype_kernel<<<1, 32>>>((const unsigned long long*)ei, probeWords);
    zero_deg_kernel<<<nodeBlocks, TB>>>(deg, n);
    decode_count_kernel<<<edgeBlocks, TB>>>(ei, esd, deg, E, n);
    scan_block_sums<<<nodeBlocks, TB>>>(deg, bsum, n);
    scan_bsums_kernel<<<1, 1024>>>(bsum, nodeBlocks);
    scan_final_kernel<<<nodeBlocks, TB>>>(deg, bsum, rowptr, dinv, cnt, n);
    scatter_csr_kernel<<<edgeBlocks, TB>>>(esd, dinv, rowptr, cnt, csr, E);

    // Layer 1
    gemm_kernel<<<gemmBlocks, TB>>>(x, W1, (float*)h, n);
    pull_kernel<<<pullBlocks, TB>>>(csr, rowptr, deg, dinv, (const float4*)b1, h, a, n);

    // Layer 2
    gemm_kernel<<<gemmBlocks, TB>>>((const float*)a, W2, (float*)h, n);
    pull_kernel<<<pullBlocks, TB>>>(csr, rowptr, deg, dinv, (const float4*)b2, h, (float4*)out, n);
}